// round 15
// baseline (speedup 1.0000x reference)
#include <cuda_runtime.h>
#include <cstdint>

// SignedAttention R10: R9 + r=2 key blocking in phase 1 (Q broadcasts
// amortized over 2 keys/lane), key-contiguous score layout.

constexpr int Lv   = 1024;
constexpr int Dv   = 64;
constexpr int NP   = 128;
constexpr int CH   = 8;
constexpr int MAXK = 72;
constexpr int KP   = 76;   // K pitch: quad stride 19 -> CF row reads
constexpr int AP   = 80;   // at2 key pitch (dense lane access -> CF)
constexpr int TP   = 76;   // at_t pitch: CF quad reads
constexpr int NT   = 256;

using u64 = unsigned long long;

__device__ __forceinline__ void cp16(void* dst, const void* src) {
    uint32_t d = (uint32_t)__cvta_generic_to_shared(dst);
    asm volatile("cp.async.cg.shared.global [%0], [%1], 16;" :: "r"(d), "l"(src));
}
__device__ __forceinline__ void cp_commit() { asm volatile("cp.async.commit_group;"); }
__device__ __forceinline__ void cp_wait0()  { asm volatile("cp.async.wait_group 0;"); }

__device__ __forceinline__ u64 pack2(float lo, float hi) {
    u64 r; asm("mov.b64 %0, {%1, %2};" : "=l"(r) : "f"(lo), "f"(hi)); return r;
}
__device__ __forceinline__ void ffma2(u64& acc, u64 a, u64 b) {
    asm("fma.rn.f32x2 %0, %1, %2, %0;" : "+l"(acc) : "l"(a), "l"(b));
}
__device__ __forceinline__ float2 unpack2(u64 v) {
    float lo, hi; asm("mov.b64 {%0, %1}, %2;" : "=f"(lo), "=f"(hi) : "l"(v));
    return make_float2(lo, hi);
}

__global__ __launch_bounds__(NT, 4)
void signed_attn_kernel(const float* __restrict__ Q,
                        const float* __restrict__ K,
                        const float* __restrict__ V,
                        const float* __restrict__ LS,
                        float* __restrict__ O)
{
    __shared__ float qs[CH][Dv];           // 2 KB
    __shared__ float ks[MAXK][KP];         // 21.4 KB
    __shared__ float at2[2][CH][AP];       // 5 KB : raw score halves [h][q][key]
    __shared__ float at_t[CH][TP];         // 2.4 KB : weights [q][key]
    __shared__ float part[CH][Dv];         // 2 KB : phase-3 partials  (~33.5 KB total)

    const int bh   = blockIdx.x / NP;
    const int p    = blockIdx.x % NP;
    const int tid  = threadIdx.x;
    const int warp = tid >> 5;
    const int lane = tid & 31;

    const size_t qbase = ((size_t)bh * Lv + (size_t)p * CH) * Dv;

    const int npk = min(9, NP - 1 - p);
    const int nk  = npk * CH;              // multiple of 8, 0..72

    if (nk == 0) {                         // last patch: A == 0 exactly
        O[qbase + tid]      = 0.0f;
        O[qbase + tid + NT] = 0.0f;
        return;
    }

    // ---- stage Q + K via cp.async (V is NOT staged) ----
    const size_t kbase = ((size_t)bh * Lv + (size_t)(p + 1) * CH) * Dv;
    const int n4 = nk * (Dv / 4);
    {
        if (tid < (CH * Dv) / 4) {
            int r = tid >> 4, c = tid & 15;
            cp16(&qs[r][c * 4], (const float4*)(Q + qbase) + tid);
        }
        const float4* Kg = (const float4*)(K + kbase);
        for (int idx = tid; idx < n4; idx += NT) {
            int r = idx >> 4, c = idx & 15;
            cp16(&ks[r][c * 4], Kg + idx);
        }
        cp_commit();
    }

    const float scale = fminf(fmaxf(expf(LS[0]), 1.0f), 30.0f) * 0.125f;

    cp_wait0();
    __syncthreads();

    // ---- phase 1: 4 warps = (d-half h) x (key-half kh); r=2 keys/lane ----
    // key-half 0: main keys lane (0..31), tail keys 32..35 on lanes 0..3.
    // key-half 1: main keys 36+lane (36..67), tail keys 68..71 on lanes 0..3.
    if (warp < 4) {
        const int h    = warp >> 1;
        const int kh   = warp & 1;
        const int key0 = kh * 36 + lane;           // main key (<= 67)
        const int key1 = kh * 36 + 32 + lane;      // tail key (lanes 0..3)
        const bool t1  = (lane < 4);
        const int k0c  = (key0 < nk) ? key0 : 0;   // clamp: garbage ok, never read
        const int k1c  = (t1 && key1 < nk) ? key1 : 0;

        u64 acc0[CH] = {0,0,0,0,0,0,0,0};          // d-packed (even,odd) per q
        u64 acc1[CH] = {0,0,0,0,0,0,0,0};

        const int db = h * 8;
        #pragma unroll
        for (int dd = 0; dd < 8; dd++) {
            const int c = (db + dd) * 4;
            const float4 kf0 = *(const float4*)&ks[k0c][c];
            const float4 kf1 = *(const float4*)&ks[k1c][c];
            const u64 k0a = pack2(kf0.x, kf0.y);
            const u64 k0b = pack2(kf0.z, kf0.w);
            const u64 k1a = pack2(kf1.x, kf1.y);
            const u64 k1b = pack2(kf1.z, kf1.w);
            #pragma unroll
            for (int qi = 0; qi < CH; qi++) {
                const float4 qf = *(const float4*)&qs[qi][c];
                const u64 qa = pack2(qf.x, qf.y);
                const u64 qb = pack2(qf.z, qf.w);
                ffma2(acc0[qi], qa, k0a);
                ffma2(acc0[qi], qb, k0b);
                ffma2(acc1[qi], qa, k1a);
                ffma2(acc1[qi], qb, k1b);
            }
        }
        #pragma unroll
        for (int qi = 0; qi < CH; qi++) {
            const float2 s0 = unpack2(acc0[qi]);
            at2[h][qi][key0] = s0.x + s0.y;        // dense 128B store: 1 wf
            if (t1) {
                const float2 s1 = unpack2(acc1[qi]);
                at2[h][qi][key1] = s1.x + s1.y;    // 16B partial: 1 wf
            }
        }
    }
    __syncthreads();

    // ---- phase 2: warp q -> dual softmax (adds d-halves); write transposed ----
    {
        const int q = warp;
        const bool v0 = (lane      < nk);
        const bool v1 = (lane + 32 < nk);
        const bool v2 = (lane + 64 < nk);
        const float t0 = v0 ? (at2[0][q][lane     ] + at2[1][q][lane     ]) * scale : 0.0f;
        const float t1 = v1 ? (at2[0][q][lane + 32] + at2[1][q][lane + 32]) * scale : 0.0f;
        const float t2 = v2 ? (at2[0][q][lane + 64] + at2[1][q][lane + 64]) * scale : 0.0f;

        float mx = -1e30f, mn = 1e30f;
        if (v0) { mx = fmaxf(mx, t0); mn = fminf(mn, t0); }
        if (v1) { mx = fmaxf(mx, t1); mn = fminf(mn, t1); }
        if (v2) { mx = fmaxf(mx, t2); mn = fminf(mn, t2); }
        #pragma unroll
        for (int o = 16; o; o >>= 1) {
            mx = fmaxf(mx, __shfl_xor_sync(0xffffffffu, mx, o));
            mn = fminf(mn, __shfl_xor_sync(0xffffffffu, mn, o));
        }

        float sp = 0.0f, sn = 0.0f;
        float e0p=0, e0n=0, e1p=0, e1n=0, e2p=0, e2n=0;
        if (v0) { e0p = __expf(t0 - mx); e0n = __expf(mn - t0); sp += e0p; sn += e0n; }
        if (v1) { e1p = __expf(t1 - mx); e1n = __expf(mn - t1); sp += e1p; sn += e1n; }
        if (v2) { e2p = __expf(t2 - mx); e2n = __expf(mn - t2); sp += e2p; sn += e2n; }
        #pragma unroll
        for (int o = 16; o; o >>= 1) {
            sp += __shfl_xor_sync(0xffffffffu, sp, o);
            sn += __shfl_xor_sync(0xffffffffu, sn, o);
        }
        const float rp = 1.0f / sp;
        const float rn = 1.0f / sn;
        if (v0) at_t[q][lane     ] = e0p * rp - e0n * rn;
        if (v1) at_t[q][lane + 32] = e1p * rp - e1n * rn;
        if (v2) at_t[q][lane + 64] = e2p * rp - e2n * rn;
    }
    __syncthreads();

    // ---- phase 3: key-halves x 16-wide d-slices; V direct LDG, FFMA2 ----
    {
        const int w4   = warp & 3;
        const int q    = lane >> 2;                     // 0..7
        const int dof  = w4 * 16 + (lane & 3) * 4;      // float4 slice
        const int half = nk >> 1;                       // multiple of 4
        const int j0   = (warp >= 4) ? half : 0;
        const int j1   = j0 + half;

        const float4* __restrict__ Vg =
            (const float4*)(V + kbase + dof) + (size_t)j0 * (Dv / 4);

        u64 a01 = 0, a23 = 0;                           // packed d-pair accs
        #pragma unroll 4
        for (int j = j0; j < j1; j += 4) {
            const float4 a4 = *(const float4*)&at_t[q][j];   // CF quad read
            float4 vv; u64 aa;
            vv = Vg[0 * (Dv / 4)]; aa = pack2(a4.x, a4.x);
            ffma2(a01, pack2(vv.x, vv.y), aa);
            ffma2(a23, pack2(vv.z, vv.w), aa);
            vv = Vg[1 * (Dv / 4)]; aa = pack2(a4.y, a4.y);
            ffma2(a01, pack2(vv.x, vv.y), aa);
            ffma2(a23, pack2(vv.z, vv.w), aa);
            vv = Vg[2 * (Dv / 4)]; aa = pack2(a4.z, a4.z);
            ffma2(a01, pack2(vv.x, vv.y), aa);
            ffma2(a23, pack2(vv.z, vv.w), aa);
            vv = Vg[3 * (Dv / 4)]; aa = pack2(a4.w, a4.w);
            ffma2(a01, pack2(vv.x, vv.y), aa);
            ffma2(a23, pack2(vv.z, vv.w), aa);
            Vg += 4 * (Dv / 4);
        }
        const float2 e01 = unpack2(a01);
        const float2 e23 = unpack2(a23);
        float4 acc = make_float4(e01.x, e01.y, e23.x, e23.y);

        if (warp >= 4)
            *(float4*)&part[q][dof] = acc;
        __syncthreads();
        if (warp < 4) {
            const float4 pp = *(const float4*)&part[q][dof];
            acc.x += pp.x; acc.y += pp.y; acc.z += pp.z; acc.w += pp.w;
            *(float4*)(O + qbase + (size_t)q * Dv + dof) = acc;
        }
    }
}

extern "C" void kernel_launch(void* const* d_in, const int* in_sizes, int n_in,
                              void* d_out, int out_size)
{
    const float* Q  = (const float*)d_in[0];
    const float* K  = (const float*)d_in[1];
    const float* V  = (const float*)d_in[2];
    const float* LS = (const float*)d_in[3];
    float* O = (float*)d_out;

    const int BH = in_sizes[0] / (Lv * Dv);   // B*H = 32
    signed_attn_kernel<<<BH * NP, NT>>>(Q, K, V, LS, O);
}